// round 2
// baseline (speedup 1.0000x reference)
#include <cuda_runtime.h>
#include <math_constants.h>

// Problem: loss over three persistence diagrams, each (8M, 2) f32.
//   l = dgm[:,0] - dgm[:,1], nonfinite -> 0
//   top1 = max(l0); t01 = 1 - top1^2; t0 = sum(l0^2) - top1^2
//   t1 = sum(l1^2); t2 = sum(l2^2); loss = t01+t0+t1+t2
// Output: 5 f32 scalars (loss, t01, t0, t1, t2).
// Pure HBM-bound reduction: 192 MiB in, 20 B out.

#define BPA 512            // blocks per array
#define THREADS 256

__device__ float g_part_sum[3 * BPA];
__device__ float g_part_max[BPA];

__global__ __launch_bounds__(THREADS) void toploss_pass1(
    const float4* __restrict__ d0,
    const float4* __restrict__ d1,
    const float4* __restrict__ d2,
    int n4)
{
    const int arr = blockIdx.x / BPA;
    const int b   = blockIdx.x % BPA;
    const float4* __restrict__ p = (arr == 0) ? d0 : ((arr == 1) ? d1 : d2);

    float sum = 0.0f;
    float mx  = -CUDART_INF_F;

    const int stride = BPA * THREADS;
    for (int i = b * THREADS + threadIdx.x; i < n4; i += stride) {
        float4 v = p[i];
        float la = v.x - v.y;
        float lb = v.z - v.w;
        if (!isfinite(la)) la = 0.0f;
        if (!isfinite(lb)) lb = 0.0f;
        sum = fmaf(la, la, sum);
        sum = fmaf(lb, lb, sum);
        mx  = fmaxf(mx, fmaxf(la, lb));
    }

    // block reduction
    __shared__ float ssum[THREADS];
    __shared__ float smax[THREADS];
    const int tid = threadIdx.x;
    ssum[tid] = sum;
    smax[tid] = mx;
    __syncthreads();
    #pragma unroll
    for (int off = THREADS / 2; off >= 32; off >>= 1) {
        if (tid < off) {
            ssum[tid] += ssum[tid + off];
            smax[tid]  = fmaxf(smax[tid], smax[tid + off]);
        }
        __syncthreads();
    }
    if (tid < 32) {
        float s = ssum[tid];
        float m = smax[tid];
        #pragma unroll
        for (int off = 16; off > 0; off >>= 1) {
            s += __shfl_down_sync(0xFFFFFFFFu, s, off);
            m  = fmaxf(m, __shfl_down_sync(0xFFFFFFFFu, m, off));
        }
        if (tid == 0) {
            g_part_sum[arr * BPA + b] = s;
            if (arr == 0) g_part_max[b] = m;
        }
    }
}

__global__ __launch_bounds__(BPA) void toploss_finalize(float* __restrict__ out)
{
    const int tid = threadIdx.x;   // BPA threads, one per block-partial
    float s0 = g_part_sum[0 * BPA + tid];
    float s1 = g_part_sum[1 * BPA + tid];
    float s2 = g_part_sum[2 * BPA + tid];
    float m  = g_part_max[tid];

    __shared__ float sh0[BPA], sh1[BPA], sh2[BPA], shm[BPA];
    sh0[tid] = s0; sh1[tid] = s1; sh2[tid] = s2; shm[tid] = m;
    __syncthreads();
    #pragma unroll
    for (int off = BPA / 2; off >= 32; off >>= 1) {
        if (tid < off) {
            sh0[tid] += sh0[tid + off];
            sh1[tid] += sh1[tid + off];
            sh2[tid] += sh2[tid + off];
            shm[tid]  = fmaxf(shm[tid], shm[tid + off]);
        }
        __syncthreads();
    }
    if (tid < 32) {
        float a = sh0[tid], b = sh1[tid], c = sh2[tid], mm = shm[tid];
        #pragma unroll
        for (int off = 16; off > 0; off >>= 1) {
            a += __shfl_down_sync(0xFFFFFFFFu, a, off);
            b += __shfl_down_sync(0xFFFFFFFFu, b, off);
            c += __shfl_down_sync(0xFFFFFFFFu, c, off);
            mm = fmaxf(mm, __shfl_down_sync(0xFFFFFFFFu, mm, off));
        }
        if (tid == 0) {
            float top1 = mm;
            float t01  = 1.0f - top1 * top1;
            float t0   = a - top1 * top1;
            float t1   = b;
            float t2   = c;
            float loss = t01 + t0 + t1 + t2;
            out[0] = loss;
            out[1] = t01;
            out[2] = t0;
            out[3] = t1;
            out[4] = t2;
        }
    }
}

extern "C" void kernel_launch(void* const* d_in, const int* in_sizes, int n_in,
                              void* d_out, int out_size)
{
    const float4* d0 = (const float4*)d_in[0];
    const float4* d1 = (const float4*)d_in[1];
    const float4* d2 = (const float4*)d_in[2];
    float* out = (float*)d_out;

    // in_sizes[i] is the element count of the flattened (N,2) f32 array.
    const int n4 = in_sizes[0] / 4;   // float4s per array (2 pairs each)

    toploss_pass1<<<3 * BPA, THREADS>>>(d0, d1, d2, n4);
    toploss_finalize<<<1, BPA>>>(out);
}

// round 3
// speedup vs baseline: 1.0069x; 1.0069x over previous
#include <cuda_runtime.h>
#include <math_constants.h>

// loss over three persistence diagrams, each (8M, 2) f32.
//   l = dgm[:,0] - dgm[:,1], nonfinite -> 0
//   top1 = max(l0); t01 = 1 - top1^2; t0 = sum(l0^2) - top1^2
//   t1 = sum(l1^2); t2 = sum(l2^2); loss = t01+t0+t1+t2
// Single fused kernel: grid-stride squared-sum/max partials per block,
// last-block-done finalize (no second launch).

#define BPA 512            // blocks per array
#define THREADS 256
#define NBLOCKS (3 * BPA)

__device__ float g_part_sum[3 * BPA];
__device__ float g_part_max[BPA];
__device__ unsigned int g_done = 0;

__device__ __forceinline__ float bar_len2_acc(float4 v, float& mx, float acc)
{
    float la = v.x - v.y;
    float lb = v.z - v.w;
    if (!isfinite(la)) la = 0.0f;
    if (!isfinite(lb)) lb = 0.0f;
    mx  = fmaxf(mx, fmaxf(la, lb));
    acc = fmaf(la, la, acc);
    acc = fmaf(lb, lb, acc);
    return acc;
}

__global__ __launch_bounds__(THREADS) void toploss_fused(
    const float4* __restrict__ d0,
    const float4* __restrict__ d1,
    const float4* __restrict__ d2,
    float* __restrict__ out,
    int n4)
{
    const int arr = blockIdx.x / BPA;
    const int b   = blockIdx.x % BPA;
    const int tid = threadIdx.x;
    const float4* __restrict__ p = (arr == 0) ? d0 : ((arr == 1) ? d1 : d2);

    const int stride = BPA * THREADS;

    float s0 = 0.0f, s1 = 0.0f, s2 = 0.0f, s3 = 0.0f;
    float m0 = -CUDART_INF_F, m1 = -CUDART_INF_F;
    float m2 = -CUDART_INF_F, m3 = -CUDART_INF_F;

    int i = b * THREADS + tid;
    // Unrolled x4: four independent streaming loads in flight per trip.
    for (; i + 3 * stride < n4; i += 4 * stride) {
        float4 v0 = __ldcs(&p[i]);
        float4 v1 = __ldcs(&p[i + stride]);
        float4 v2 = __ldcs(&p[i + 2 * stride]);
        float4 v3 = __ldcs(&p[i + 3 * stride]);
        s0 = bar_len2_acc(v0, m0, s0);
        s1 = bar_len2_acc(v1, m1, s1);
        s2 = bar_len2_acc(v2, m2, s2);
        s3 = bar_len2_acc(v3, m3, s3);
    }
    for (; i < n4; i += stride) {
        float4 v = __ldcs(&p[i]);
        s0 = bar_len2_acc(v, m0, s0);
    }

    float sum = (s0 + s1) + (s2 + s3);
    float mx  = fmaxf(fmaxf(m0, m1), fmaxf(m2, m3));

    // ---- block reduction ----
    __shared__ float ssum[THREADS];
    __shared__ float smax[THREADS];
    ssum[tid] = sum;
    smax[tid] = mx;
    __syncthreads();
    #pragma unroll
    for (int off = THREADS / 2; off >= 32; off >>= 1) {
        if (tid < off) {
            ssum[tid] += ssum[tid + off];
            smax[tid]  = fmaxf(smax[tid], smax[tid + off]);
        }
        __syncthreads();
    }
    if (tid < 32) {
        float s = ssum[tid];
        float m = smax[tid];
        #pragma unroll
        for (int off = 16; off > 0; off >>= 1) {
            s += __shfl_down_sync(0xFFFFFFFFu, s, off);
            m  = fmaxf(m, __shfl_down_sync(0xFFFFFFFFu, m, off));
        }
        if (tid == 0) {
            g_part_sum[arr * BPA + b] = s;
            if (arr == 0) g_part_max[b] = m;
        }
    }

    // ---- last-block-done finalize ----
    __shared__ bool s_last;
    __syncthreads();
    if (tid == 0) {
        __threadfence();
        unsigned int prev = atomicAdd(&g_done, 1u);
        s_last = (prev == NBLOCKS - 1);
    }
    __syncthreads();
    if (!s_last) return;

    // This (single) block reduces the 3*BPA sum partials + BPA max partials.
    // Each thread owns BPA/THREADS = 2 partials per array.
    float a0 = 0.0f, a1 = 0.0f, a2 = 0.0f;
    float fm = -CUDART_INF_F;
    #pragma unroll
    for (int k = tid; k < BPA; k += THREADS) {
        a0 += g_part_sum[0 * BPA + k];
        a1 += g_part_sum[1 * BPA + k];
        a2 += g_part_sum[2 * BPA + k];
        fm  = fmaxf(fm, g_part_max[k]);
    }

    __shared__ float sh0[THREADS], sh1[THREADS], sh2[THREADS], shm[THREADS];
    sh0[tid] = a0; sh1[tid] = a1; sh2[tid] = a2; shm[tid] = fm;
    __syncthreads();
    #pragma unroll
    for (int off = THREADS / 2; off >= 32; off >>= 1) {
        if (tid < off) {
            sh0[tid] += sh0[tid + off];
            sh1[tid] += sh1[tid + off];
            sh2[tid] += sh2[tid + off];
            shm[tid]  = fmaxf(shm[tid], shm[tid + off]);
        }
        __syncthreads();
    }
    if (tid < 32) {
        float x = sh0[tid], y = sh1[tid], z = sh2[tid], mm = shm[tid];
        #pragma unroll
        for (int off = 16; off > 0; off >>= 1) {
            x += __shfl_down_sync(0xFFFFFFFFu, x, off);
            y += __shfl_down_sync(0xFFFFFFFFu, y, off);
            z += __shfl_down_sync(0xFFFFFFFFu, z, off);
            mm = fmaxf(mm, __shfl_down_sync(0xFFFFFFFFu, mm, off));
        }
        if (tid == 0) {
            float top1 = mm;
            float t01  = 1.0f - top1 * top1;
            float t0   = x - top1 * top1;
            float loss = t01 + t0 + y + z;
            out[0] = loss;
            out[1] = t01;
            out[2] = t0;
            out[3] = y;
            out[4] = z;
            g_done = 0;   // reset for next graph replay
        }
    }
}

extern "C" void kernel_launch(void* const* d_in, const int* in_sizes, int n_in,
                              void* d_out, int out_size)
{
    const float4* d0 = (const float4*)d_in[0];
    const float4* d1 = (const float4*)d_in[1];
    const float4* d2 = (const float4*)d_in[2];
    float* out = (float*)d_out;

    const int n4 = in_sizes[0] / 4;   // float4s per array (2 bars each)

    toploss_fused<<<NBLOCKS, THREADS>>>(d0, d1, d2, out, n4);
}